// round 7
// baseline (speedup 1.0000x reference)
#include <cuda_runtime.h>
#include <math.h>

#define NEGV (-1e30f)
#define LN2F 0.6931471805599453f

// scratch (no cudaMalloc allowed): class-major raw probs, [B][C][T], T=1024
#define TMAX 1024
__device__ float g_pt[64 * 128 * TMAX];
__device__ float g_loss[4096];
__device__ unsigned int g_ctr;   // wraps back to 0 every launch via atomicInc

__device__ __forceinline__ float ex2(float x) {
    float r; asm("ex2.approx.f32 %0, %1;" : "=f"(r) : "f"(x)); return r;
}
__device__ __forceinline__ float lg2(float x) {
    float r; asm("lg2.approx.f32 %0, %1;" : "=f"(r) : "f"(x)); return r;
}

// ---------------------------------------------------------------------------
// Kernel 1: fused  out[t][b][c] = log(p[b][t][c])  AND  g_pt[b][c][t] = p[b][t][c]
// Tiled 32x32 transpose per (b, t-tile, c-tile). Block 32x8, 4 row-iterations.
// ---------------------------------------------------------------------------
__global__ void __launch_bounds__(256)
prep_kernel(const float* __restrict__ p, float* __restrict__ out,
            int T, int B, int C) {
    __shared__ float tile[32][33];
    const int tx = threadIdx.x;          // 0..31
    const int ty = threadIdx.y;          // 0..7
    const int c0 = blockIdx.x * 32;
    const int t0 = blockIdx.y * 32;
    const int b  = blockIdx.z;

    #pragma unroll
    for (int i = 0; i < 4; ++i) {
        int t = t0 + ty + i * 8;
        int c = c0 + tx;
        float v = p[((long long)b * T + t) * C + c];
        tile[ty + i * 8][tx] = v;
        out[(((long long)t * B + b) * C) + c] = __logf(v);
    }
    __syncthreads();
    #pragma unroll
    for (int i = 0; i < 4; ++i) {
        int c = c0 + ty + i * 8;
        g_pt[(((long long)b * C + c) << 10) + t0 + tx] = tile[tx][ty + i * 8];
    }
}

// ---------------------------------------------------------------------------
// Kernel 2: CTC forward (log2 domain, register alphas, 1 barrier/step).
// Thread tid owns states 2tid (blank/even) and 2tid+1 (label/odd);
// the last thread additionally owns state 2L (final blank).
// Probability streams read from g_pt: per thread ONE float4 per 4 steps.
// ---------------------------------------------------------------------------
__global__ void __launch_bounds__(256)
ctc_kernel(const int* __restrict__ labels,   // [B,L]
           const int* __restrict__ in_len,   // [B]
           const int* __restrict__ lab_len,  // [B]
           float* __restrict__ out,          // loss written at loss_idx
           int T, int B, int C, int L, long long loss_idx) {
    __shared__ float bnd[2][8];
    __shared__ float sA[513];

    const int b    = blockIdx.x;
    const int tid  = threadIdx.x;
    const int w    = tid >> 5;
    const int lane = tid & 31;
    const int last = blockDim.x - 1;

    int il = in_len[b];  il = il < 1 ? 1 : (il > T ? T : il);
    int ll = lab_len[b]; ll = ll < 1 ? 1 : (ll > L ? L : ll);

    const int  lab  = labels[b * L + tid];
    const bool skip = (tid > 0) && (lab != labels[b * L + tid - 1]);

    const float* __restrict__ rowB = g_pt + ((long long)b * C << 10);      // blank row
    const float* __restrict__ rowL = rowB + ((long long)lab << 10);        // label row

    // ---- t = 0 ----
    float ae, ao, a5 = NEGV;
    {
        float pb0 = __ldg(rowB);
        float pl0 = __ldg(rowL);
        ae = (tid == 0) ? lg2(pb0) : NEGV;
        ao = (tid == 0) ? lg2(pl0) : NEGV;
        if (lane == 31) bnd[1][w] = ao;      // parity for t=1
    }

    // scalar probs for t = 1..3, plus two float4 groups (t=4..7, 8..11)
    float spb[3], spl[3];
    #pragma unroll
    for (int j = 0; j < 3; ++j) {
        int tt = 1 + j; if (tt > T - 1) tt = T - 1;
        spb[j] = __ldg(rowB + tt);
        spl[j] = __ldg(rowL + tt);
    }
    float4 fb[2], fl[2];
    fb[0] = *(const float4*)(rowB + 4);   fl[0] = *(const float4*)(rowL + 4);
    fb[1] = *(const float4*)(rowB + 8);   fl[1] = *(const float4*)(rowL + 8);
    __syncthreads();

    // one timestep (log2-domain lse with prob folded into lg2)
    #define CTC_STEP(T_, PB_, PL_)                                          \
    {                                                                        \
        int t_ = (T_);                                                       \
        float pb = (PB_), pl = (PL_);                                        \
        float a_ol = __shfl_up_sync(0xffffffffu, ao, 1);                     \
        if (lane == 0) a_ol = (w > 0) ? bnd[t_ & 1][w - 1] : NEGV;           \
        float me = fmaxf(ae, a_ol);                                          \
        float ve = me + lg2((1.0f + ex2(fminf(ae, a_ol) - me)) * pb);        \
        float a2 = skip ? a_ol : NEGV;                                       \
        float mo = fmaxf(ao, fmaxf(ae, a2));                                 \
        float so = ex2(ao - mo) + ex2(ae - mo) + ex2(a2 - mo);               \
        float vo = mo + lg2(so * pl);                                        \
        if (tid == last) {                                                   \
            float m5 = fmaxf(a5, ao);                                        \
            a5 = m5 + lg2((1.0f + ex2(fminf(a5, ao) - m5)) * pb);            \
        }                                                                    \
        ae = ve; ao = vo;                                                    \
        if (lane == 31) bnd[(t_ + 1) & 1][w] = ao;                           \
        __syncthreads();                                                     \
    }

    // ---- t = 1..3 (scalar prologue) ----
    #pragma unroll
    for (int j = 0; j < 3; ++j) {
        int t = 1 + j;
        if (t >= il) break;
        CTC_STEP(t, spb[j], spl[j]);
    }

    // ---- t = 4 .. il-1, in aligned 4-step groups, double-buffered float4 ----
    int cur = 0;
    for (int tg = 4; tg < il; tg += 4) {
        float4 vb = fb[cur], vl = fl[cur];
        if (tg + 0 < il) CTC_STEP(tg + 0, vb.x, vl.x);
        if (tg + 1 < il) CTC_STEP(tg + 1, vb.y, vl.y);
        if (tg + 2 < il) CTC_STEP(tg + 2, vb.z, vl.z);
        if (tg + 3 < il) CTC_STEP(tg + 3, vb.w, vl.w);
        int tp = tg + 8;                      // refill consumed buffer
        if (tp > TMAX - 4) tp = TMAX - 4;     // rows are full T; safe to over-read
        fb[cur] = *(const float4*)(rowB + tp);
        fl[cur] = *(const float4*)(rowL + tp);
        cur ^= 1;
    }
    #undef CTC_STEP

    // ---- finalize: dump alpha, loss, fused mean via atomic counter ---------
    sA[2 * tid]     = ae;
    sA[2 * tid + 1] = ao;
    if (tid == last) sA[512] = a5;
    __syncthreads();

    if (tid == 0) {
        float e1 = sA[2 * ll - 1];
        float e2 = sA[2 * ll];
        float m  = fmaxf(e1, e2);
        float l2 = m + lg2(ex2(e1 - m) + ex2(e2 - m));
        g_loss[b] = -l2 * LN2F;
        __threadfence();
        unsigned int old = atomicInc(&g_ctr, (unsigned)(B - 1));   // wraps to 0
        if (old == (unsigned)(B - 1)) {
            __threadfence();
            volatile float* gl = g_loss;
            float s = 0.f;
            for (int i = 0; i < B; ++i) s += gl[i];
            out[loss_idx] = s / (float)B;
        }
    }
}

// ---------------------------------------------------------------------------
extern "C" void kernel_launch(void* const* d_in, const int* in_sizes, int n_in,
                              void* d_out, int out_size) {
    const int*   y_true = (const int*)  d_in[0];  // [B, L]
    const float* y_pred = (const float*)d_in[1];  // [B, T, C]
    const int*   il     = (const int*)  d_in[2];  // [B]
    const int*   ll     = (const int*)  d_in[3];  // [B]

    const int B = in_sizes[2];
    const int L = in_sizes[0] / B;                // 256
    const int C = 128;                            // fixed for this problem
    const int T = in_sizes[1] / (B * C);          // 1024
    float* out = (float*)d_out;

    // 1) fused log-transpose (output) + class-major scratch fill
    {
        dim3 grid(C / 32, T / 32, B);             // (4, 32, 64)
        dim3 block(32, 8);
        prep_kernel<<<grid, block>>>(y_pred, out, T, B, C);
    }
    // 2) CTC forward + fused mean
    ctc_kernel<<<B, L>>>(y_true, il, ll, out, T, B, C, L,
                         (long long)out_size - 1);
}